// round 16
// baseline (speedup 1.0000x reference)
#include <cuda_runtime.h>
#include <cuda_bf16.h>
#include <math_constants.h>
#include <cstdint>

#define DM   1024
#define HS   64
#define BB   4
#define TT   2048
#define ROWS (BB * TT)        /* 8192 */
#define NS   8                /* key splits (SPLIT = 256) */
#define SPLIT 256
#define TRI2 72               /* sum ceil((qt+1)/2), qt=0..15 */
#define NCOL 192
#define SCV  11.541560327111707f   /* 8 * log2(e) */
#define QBUF 40960            /* qkv per-buffer smem */

typedef unsigned long long u64;

/* ---------------- helpers ------------------------------------------------ */
__device__ __forceinline__ unsigned pk_bf2(float a, float b) {
    unsigned r;
    asm("cvt.rn.bf16x2.f32 %0, %1, %2;" : "=r"(r) : "f"(b), "f"(a));
    return r;
}
__device__ __forceinline__ void mma_bf16(float* d, const unsigned* a, const unsigned* b) {
    asm volatile(
        "mma.sync.aligned.m16n8k16.row.col.f32.bf16.bf16.f32 "
        "{%0,%1,%2,%3}, {%4,%5,%6,%7}, {%8,%9}, {%0,%1,%2,%3};"
        : "+f"(d[0]), "+f"(d[1]), "+f"(d[2]), "+f"(d[3])
        : "r"(a[0]), "r"(a[1]), "r"(a[2]), "r"(a[3]), "r"(b[0]), "r"(b[1]));
}
__device__ __forceinline__ void ldsm_x4(unsigned* r, uint32_t addr) {
    asm volatile("ldmatrix.sync.aligned.m8n8.x4.shared.b16 {%0,%1,%2,%3}, [%4];"
        : "=r"(r[0]), "=r"(r[1]), "=r"(r[2]), "=r"(r[3]) : "r"(addr));
}
__device__ __forceinline__ uint32_t smem_u32(const void* p) {
    uint32_t a;
    asm("{ .reg .u64 t; cvta.to.shared.u64 t, %1; cvt.u32.u64 %0, t; }"
        : "=r"(a) : "l"(p));
    return a;
}
__device__ __forceinline__ void split4(float4 v, u64& hi, u64& lo) {
    unsigned h01 = pk_bf2(v.x, v.y), h23 = pk_bf2(v.z, v.w);
    float h0 = __uint_as_float(h01 << 16);
    float h1 = __uint_as_float(h01 & 0xffff0000u);
    float h2 = __uint_as_float(h23 << 16);
    float h3 = __uint_as_float(h23 & 0xffff0000u);
    unsigned l01 = pk_bf2(v.x - h0, v.y - h1), l23 = pk_bf2(v.z - h2, v.w - h3);
    hi = ((u64)h23 << 32) | h01;
    lo = ((u64)l23 << 32) | l01;
}

/* ---------------- device scratch ---------------------------------------- */
__device__ u64 g_Bh[NCOL * DM / 4];
__device__ u64 g_Bl[NCOL * DM / 4];
__device__ uint16_t g_qh[ROWS * HS], g_ql[ROWS * HS];
__device__ uint16_t g_kh[ROWS * HS], g_kl[ROWS * HS];
__device__ uint16_t g_vth[BB * HS * TT], g_vtl[BB * HS * TT];
__device__ float g_po[(size_t)NS * ROWS * HS];
__device__ float g_pm[NS * ROWS];
__device__ float g_pl[NS * ROWS];

/* ---------------- build fused transposed weight B[n][k] (coalesced) ----- */
__global__ __launch_bounds__(256)
void build_b_kernel(const float* __restrict__ Wq, const float* __restrict__ Wk,
                    const float* __restrict__ Wv) {
    __shared__ float s[64][65];
    const int k0    = blockIdx.x * 64;
    const int which = blockIdx.y;
    const float* __restrict__ W = (which == 0) ? Wq : ((which == 1) ? Wk : Wv);

    #pragma unroll
    for (int t = 0; t < 16; t++) {
        int idx = threadIdx.x + t * 256;
        int r = idx >> 6, c = idx & 63;
        s[r][c] = W[(size_t)(k0 + r) * HS + c];
    }
    __syncthreads();

    uint16_t* dh = (uint16_t*)g_Bh;
    uint16_t* dl = (uint16_t*)g_Bl;
    #pragma unroll
    for (int t = 0; t < 16; t++) {
        int idx = threadIdx.x + t * 256;
        int n = idx >> 6, k = idx & 63;
        float v = s[k][n];
        unsigned hp = pk_bf2(v, 0.f);
        float h = __uint_as_float(hp << 16);
        unsigned lp = pk_bf2(v - h, 0.f);
        size_t o = (size_t)(which * 64 + n) * DM + k0 + k;
        dh[o] = (uint16_t)(hp & 0xffffu);
        dl[o] = (uint16_t)(lp & 0xffffu);
    }
}

/* ---------------- fused QKV GEMM: M=64, N=192, double smem buffer --------
 * Plain LDG reg-prefetch (round-11 style), STS alternates buffers ->
 * ONE __syncthreads per chunk. Dynamic smem 2 x 40960.
 * Per buffer: Ah@0 (5120) Al@5120 Bh@10240 (15360) Bl@25600 (15360). */
#define QPITCH 80
#define TPITCH 132
__global__ __launch_bounds__(256)
void qkv_mma_kernel(const float* __restrict__ x,
                    const float* __restrict__ bq, const float* __restrict__ bk) {
    extern __shared__ __align__(128) uint8_t dsm[];

    const int tid  = threadIdx.x;
    const int row0 = blockIdx.x * 64;
    const int w    = tid >> 5;
    const int lane = tid & 31;
    const int wm   = w & 1;
    const int wn   = w >> 1;
    const int g    = lane >> 2;
    const int tig  = lane & 3;
    const int l7   = lane & 7;
    const int q01  = (lane >> 3) & 1;
    const int q2   = lane >> 4;
    const uint32_t sb = smem_u32(dsm);

    const int arow = tid >> 2, aseg = tid & 3;
    int brow_[3], bseg_[3];
    #pragma unroll
    for (int t = 0; t < 3; t++) { int i = tid + t * 256; brow_[t] = i >> 2; bseg_[t] = i & 3; }

    float acc[2][6][4];
    #pragma unroll
    for (int mt = 0; mt < 2; mt++)
        #pragma unroll
        for (int nt = 0; nt < 6; nt++)
            #pragma unroll
            for (int e = 0; e < 4; e++) acc[mt][nt][e] = 0.f;

    float4 fa[2][2];
    ulonglong2 rb[2][2][3];     /* [set][hi/lo][item] */

    #define LDGC(cv, s_) do {                                                      \
        const float* _ap = x + (size_t)(row0 + arow) * DM + (cv) * 32 + aseg * 8;  \
        fa[s_][0] = *(const float4*)_ap;                                           \
        fa[s_][1] = *(const float4*)(_ap + 4);                                     \
        _Pragma("unroll")                                                          \
        for (int _t = 0; _t < 3; _t++) {                                           \
            size_t _o = (size_t)brow_[_t] * 256 + (cv) * 8 + bseg_[_t] * 2;        \
            rb[s_][0][_t] = *(const ulonglong2*)(g_Bh + _o);                       \
            rb[s_][1][_t] = *(const ulonglong2*)(g_Bl + _o);                       \
        }                                                                          \
    } while (0)

    #define STSC(s_, dbase8) do {                                                  \
        uint8_t* _bp = (dbase8);                                                   \
        u64 _h0, _l0, _h1, _l1;                                                    \
        split4(fa[s_][0], _h0, _l0);                                               \
        split4(fa[s_][1], _h1, _l1);                                               \
        ulonglong2 _vh; _vh.x = _h0; _vh.y = _h1;                                  \
        ulonglong2 _vl; _vl.x = _l0; _vl.y = _l1;                                  \
        *(ulonglong2*)(_bp + arow * QPITCH + aseg * 16)        = _vh;              \
        *(ulonglong2*)(_bp + 5120 + arow * QPITCH + aseg * 16) = _vl;              \
        _Pragma("unroll")                                                          \
        for (int _t = 0; _t < 3; _t++) {                                           \
            *(ulonglong2*)(_bp + 10240 + brow_[_t] * QPITCH + bseg_[_t] * 16) = rb[s_][0][_t]; \
            *(ulonglong2*)(_bp + 25600 + brow_[_t] * QPITCH + bseg_[_t] * 16) = rb[s_][1][_t]; \
        }                                                                          \
    } while (0)

    /* prologue: chunk0 -> regs -> buf0; chunk1 -> regs */
    LDGC(0, 0);
    STSC(0, dsm);
    LDGC(1, 1);

    for (int c = 0; c < 32; c++) {
        const int cur = c & 1;
        const uint32_t bb = sb + cur * QBUF;
        __syncthreads();                 /* publish STS(c); MMA(c-1) complete */

        if (c + 1 < 32) {
            STSC((c + 1) & 1, dsm + (1 - cur) * QBUF);
            if (c + 2 < 32) LDGC(c + 2, c & 1);
        }

        #pragma unroll
        for (int ks = 0; ks < 2; ks++) {
            unsigned ah[2][4], al[2][4], bh6[3][4], bl6[3][4];
            #pragma unroll
            for (int mt = 0; mt < 2; mt++) {
                uint32_t aoff = bb + (uint32_t)((wm * 32 + mt * 16 + q01 * 8 + l7) * QPITCH
                                                + ks * 32 + q2 * 16);
                ldsm_x4(ah[mt], aoff);
                ldsm_x4(al[mt], aoff + 5120);
            }
            #pragma unroll
            for (int p = 0; p < 3; p++) {
                uint32_t boff = bb + 10240 + (uint32_t)((wn * 48 + p * 16 + q2 * 8 + l7) * QPITCH
                                                        + ks * 32 + q01 * 16);
                ldsm_x4(bh6[p], boff);
                ldsm_x4(bl6[p], boff + 15360);
            }
            #pragma unroll
            for (int mt = 0; mt < 2; mt++)
                #pragma unroll
                for (int nt = 0; nt < 6; nt++) {
                    const unsigned* bh = &bh6[nt >> 1][(nt & 1) * 2];
                    const unsigned* bl = &bl6[nt >> 1][(nt & 1) * 2];
                    mma_bf16(acc[mt][nt], ah[mt], bh);
                    mma_bf16(acc[mt][nt], ah[mt], bl);
                    mma_bf16(acc[mt][nt], al[mt], bh);
                }
        }
    }
    #undef LDGC
    #undef STSC

    __syncthreads();                     /* all MMA reads done; reuse dsm */
    float* sT = (float*)dsm;

    #pragma unroll
    for (int mt = 0; mt < 2; mt++) {
        #pragma unroll
        for (int nt = 0; nt < 6; nt++) {
            int n_g = wn * 48 + nt * 8;
            int ml  = wm * 32 + mt * 16 + g;
            if (n_g < 128) {
                int which = n_g >> 6;
                int n = (n_g & 63) + tig * 2;
                uint16_t* dh = which ? g_kh : g_qh;
                uint16_t* dl = which ? g_kl : g_ql;
                const float* bias = which ? bk : bq;
                int m = row0 + ml;
                float bx = bias[n], by = bias[n + 1];
                float v0x = acc[mt][nt][0] + bx, v0y = acc[mt][nt][1] + by;
                float v1x = acc[mt][nt][2] + bx, v1y = acc[mt][nt][3] + by;
                unsigned h0 = pk_bf2(v0x, v0y);
                unsigned h1 = pk_bf2(v1x, v1y);
                float h0x = __uint_as_float(h0 << 16);
                float h0y = __uint_as_float(h0 & 0xffff0000u);
                float h1x = __uint_as_float(h1 << 16);
                float h1y = __uint_as_float(h1 & 0xffff0000u);
                *(unsigned*)&dh[(size_t)m * HS + n]       = h0;
                *(unsigned*)&dl[(size_t)m * HS + n]       = pk_bf2(v0x - h0x, v0y - h0y);
                *(unsigned*)&dh[(size_t)(m + 8) * HS + n] = h1;
                *(unsigned*)&dl[(size_t)(m + 8) * HS + n] = pk_bf2(v1x - h1x, v1y - h1y);
            } else {
                int nl = (n_g - 128) + tig * 2;
                sT[nl * TPITCH + ml]           = acc[mt][nt][0];
                sT[(nl + 1) * TPITCH + ml]     = acc[mt][nt][1];
                sT[nl * TPITCH + ml + 8]       = acc[mt][nt][2];
                sT[(nl + 1) * TPITCH + ml + 8] = acc[mt][nt][3];
            }
        }
    }
    __syncthreads();
    {
        const int b  = row0 >> 11;
        const int t0 = row0 & (TT - 1);
        #pragma unroll
        for (int t4 = 0; t4 < 4; t4++) {
            int idx = tid + t4 * 256;
            int d = idx >> 4, j = idx & 15;
            float4 v = *(const float4*)&sT[d * TPITCH + 4 * j];
            u64 hi, lo;
            split4(v, hi, lo);
            size_t o = ((size_t)(b * HS + d)) * TT + t0 + 4 * j;
            *(u64*)&g_vth[o] = hi;
            *(u64*)&g_vtl[o] = lo;
        }
    }
}

/* ---------------- causal flash-attention via mma.sync + ldmatrix --------
 * Round-11 body; single-split tiles (qt 0,1) write final output directly. */
__global__ __launch_bounds__(256)
void attn_mma_kernel(float* __restrict__ out) {
    int t = blockIdx.x;            /* 0..71 */
    int b = blockIdx.y;
    int qt = 0, cum = 0;
    #pragma unroll
    for (int i = 0; i < 16; i++) {
        int cnt = (i + 2) >> 1;
        if (t < cum + cnt) { qt = i; break; }
        cum += cnt;
    }
    const int kb  = t - cum;
    const int nkb = (qt + 2) >> 1;

    const int tid  = threadIdx.x;
    const int w    = tid >> 5;
    const int lane = tid & 31;
    const int g    = lane >> 2;
    const int tig  = lane & 3;
    const int r0   = qt * 128 + w * 16;
    const int bT   = b * TT;
    const int kend = qt * 128 + 128;

    __shared__ __align__(128) uint8_t sKh[64 * 144];
    __shared__ __align__(128) uint8_t sKl[64 * 144];
    __shared__ __align__(128) uint8_t sVh[64 * 144];
    __shared__ __align__(128) uint8_t sVl[64 * 144];

    const uint32_t kBh = smem_u32(sKh), kBl = smem_u32(sKl);
    const uint32_t vBh = smem_u32(sVh), vBl = smem_u32(sVl);
    const int l7 = lane & 7;
    const int q4 = lane >> 3;

    unsigned qh[4][4], ql[4][4];
    {
        const uint16_t* qah = g_qh + (size_t)(bT + r0 + g) * HS;
        const uint16_t* qal = g_ql + (size_t)(bT + r0 + g) * HS;
        #pragma unroll
        for (int kq = 0; kq < 4; kq++) {
            int c = kq * 16 + 2 * tig;
            qh[kq][0] = *(const unsigned*)(qah + c);
            qh[kq][1] = *(const unsigned*)(qah + 8 * HS + c);
            qh[kq][2] = *(const unsigned*)(qah + c + 8);
            qh[kq][3] = *(const unsigned*)(qah + 8 * HS + c + 8);
            ql[kq][0] = *(const unsigned*)(qal + c);
            ql[kq][1] = *(const unsigned*)(qal + 8 * HS + c);
            ql[kq][2] = *(const unsigned*)(qal + c + 8);
            ql[kq][3] = *(const unsigned*)(qal + 8 * HS + c + 8);
        }
    }

    float o[8][4];
    #pragma unroll
    for (int i = 0; i < 8; i++)
        #pragma unroll
        for (int e = 0; e < 4; e++) o[i][e] = 0.f;
    float m_a = -CUDART_INF_F, m_b = -CUDART_INF_F;
    float l_a = 0.f, l_b = 0.f;
    const int ra = r0 + g, rb = r0 + g + 8;

    for (int c2 = 0; c2 < 4; c2++) {
        const int j0 = kb * SPLIT + c2 * 64;
        if (j0 >= kend) break;
        __syncthreads();
        #pragma unroll
        for (int t4 = 0; t4 < 4; t4++) {
            int i = tid + t4 * 256;
            int row = i >> 4, c8 = i & 15;
            *(u64*)(sKh + row * 144 + c8 * 8) =
                *(const u64*)(g_kh + (size_t)(bT + j0 + row) * HS + c8 * 4);
            *(u64*)(sKl + row * 144 + c8 * 8) =
                *(const u64*)(g_kl + (size_t)(bT + j0 + row) * HS + c8 * 4);
            *(u64*)(sVh + row * 144 + c8 * 8) =
                *(const u64*)(g_vth + (size_t)(b * HS + row) * TT + j0 + c8 * 4);
            *(u64*)(sVl + row * 144 + c8 * 8) =
                *(const u64*)(g_vtl + (size_t)(b * HS + row) * TT + j0 + c8 * 4);
        }
        __syncthreads();

        if (j0 > r0 + 15) continue;

        float sc[8][4];
        #pragma unroll
        for (int nt = 0; nt < 8; nt++)
            #pragma unroll
            for (int e = 0; e < 4; e++) sc[nt][e] = 0.f;

        #pragma unroll
        for (int nt = 0; nt < 8; nt++) {
            unsigned kh[8], kl[8];
            uint32_t rowoff = (uint32_t)((nt * 8 + l7) * 144 + q4 * 16);
            ldsm_x4(kh,     kBh + rowoff);
            ldsm_x4(kh + 4, kBh + rowoff + 64);
            ldsm_x4(kl,     kBl + rowoff);
            ldsm_x4(kl + 4, kBl + rowoff + 64);
            #pragma unroll
            for (int kk = 0; kk < 4; kk++) {
                mma_bf16(sc[nt], qh[kk], kh + kk * 2);
                mma_bf16(sc[nt], qh[kk], kl + kk * 2);
                mma_bf16(sc[nt], ql[kk], kh + kk * 2);
            }
        }

        float mxa = -CUDART_INF_F, mxb = -CUDART_INF_F;
        #pragma unroll
        for (int nt = 0; nt < 8; nt++) {
            int jc = j0 + nt * 8 + 2 * tig;
            if (jc     > ra) sc[nt][0] = -CUDART_INF_F;
            if (jc + 1 > ra) sc[nt][1] = -CUDART_INF_F;
            if (jc     > rb) sc[nt][2] = -CUDART_INF_F;
            if (jc + 1 > rb) sc[nt][3] = -CUDART_INF_F;
            mxa = fmaxf(mxa, fmaxf(sc[nt][0], sc[nt][1]));
            mxb = fmaxf(mxb, fmaxf(sc[nt][2], sc[nt][3]));
        }
        mxa = fmaxf(mxa, __shfl_xor_sync(0xffffffffu, mxa, 1));
        mxa = fmaxf(mxa, __shfl_xor_sync(0xffffffffu, mxa, 2));
        mxb = fmaxf(mxb, __shfl_xor_sync(0xffffffffu, mxb, 1));
        mxb = fmaxf(mxb, __shfl_xor_sync(0xffffffffu, mxb, 2));

        float mna = fmaxf(m_a, mxa), mnb = fmaxf(m_b, mxb);
        float alpha_a = exp2f((m_a - mna) * SCV);
        float alpha_b = exp2f((m_b - mnb) * SCV);
        m_a = mna; m_b = mnb;

        float p[8][4];
        float laa = 0.f, lba = 0.f;
        #pragma unroll
        for (int nt = 0; nt < 8; nt++) {
            p[nt][0] = exp2f((sc[nt][0] - mna) * SCV);
            p[nt][1] = exp2f((sc[nt][1] - mna) * SCV);
            p[nt][2] = exp2f((sc[nt][2] - mnb) * SCV);
            p[nt][3] = exp2f((sc[nt][3] - mnb) * SCV);
            laa += p[nt][0] + p[nt][1];
            lba += p[nt][2] + p[nt][3];
        }
        laa += __shfl_xor_sync(0xffffffffu, laa, 1);
        laa += __shfl_xor_sync(0xffffffffu, laa, 2);
        lba += __shfl_xor_sync(0xffffffffu, lba, 1);
        lba += __shfl_xor_sync(0xffffffffu, lba, 2);
        l_a = l_a * alpha_a + laa;
        l_b = l_b * alpha_b + lba;

        #pragma unroll
        for (int nt = 0; nt < 8; nt++) {
            o[nt][0] *= alpha_a; o[nt][1] *= alpha_a;
            o[nt][2] *= alpha_b; o[nt][3] *= alpha_b;
        }

        unsigned ph[4][4], pl[4][4];
        #pragma unroll
        for (int k2 = 0; k2 < 4; k2++) {
            int n0 = 2 * k2, n1 = 2 * k2 + 1;
            #pragma unroll
            for (int e = 0; e < 4; e++) {
                int nt = (e < 2) ? n0 : n1;
                int e0 = (e & 1) ? 2 : 0;
                float pa = p[nt][e0], pb = p[nt][e0 + 1];
                unsigned hp = pk_bf2(pa, pb);
                float ha = __uint_as_float(hp << 16);
                float hb = __uint_as_float(hp & 0xffff0000u);
                ph[k2][e] = hp;
                pl[k2][e] = pk_bf2(pa - ha, pb - hb);
            }
        }

        #pragma unroll
        for (int nt = 0; nt < 8; nt++) {
            unsigned vh[8], vl[8];
            uint32_t rowoff = (uint32_t)((nt * 8 + l7) * 144 + q4 * 16);
            ldsm_x4(vh,     vBh + rowoff);
            ldsm_x4(vh + 4, vBh + rowoff + 64);
            ldsm_x4(vl,     vBl + rowoff);
            ldsm_x4(vl + 4, vBl + rowoff + 64);
            #pragma unroll
            for (int k2 = 0; k2 < 4; k2++) {
                mma_bf16(o[nt], ph[k2], vh + k2 * 2);
                mma_bf16(o[nt], ph[k2], vl + k2 * 2);
                mma_bf16(o[nt], pl[k2], vh + k2 * 2);
            }
        }
    }

    if (nkb == 1) {
        /* single split: finalize directly, no partials */
        float inv_a = 1.f / l_a, inv_b = 1.f / l_b;
        #pragma unroll
        for (int nt = 0; nt < 8; nt++) {
            *(float2*)&out[((size_t)(bT + ra)) * HS + nt * 8 + 2 * tig] =
                make_float2(o[nt][0] * inv_a, o[nt][1] * inv_a);
            *(float2*)&out[((size_t)(bT + rb)) * HS + nt * 8 + 2 * tig] =
                make_float2(o[nt][2] * inv_b, o[nt][3] * inv_b);
        }
        return;
    }

    size_t pa_off = ((size_t)kb * ROWS + bT + ra) * HS;
    size_t pb_off = ((size_t)kb * ROWS + bT + rb) * HS;
    #pragma unroll
    for (int nt = 0; nt < 8; nt++) {
        *(float2*)&g_po[pa_off + nt * 8 + 2 * tig] = make_float2(o[nt][0], o[nt][1]);
        *(float2*)&g_po[pb_off + nt * 8 + 2 * tig] = make_float2(o[nt][2], o[nt][3]);
    }
    if (tig == 0) {
        g_pm[kb * ROWS + bT + ra] = m_a * 8.0f;
        g_pl[kb * ROWS + bT + ra] = l_a;
        g_pm[kb * ROWS + bT + rb] = m_b * 8.0f;
        g_pl[kb * ROWS + bT + rb] = l_b;
    }
}

/* ---------------- combine split partials (multi-split rows only) --------- */
__global__ __launch_bounds__(256)
void attn_combine_kernel(float* __restrict__ out) {
    int t = blockIdx.x * blockDim.x + threadIdx.x;
    if (t >= ROWS * 32) return;
    int row = t >> 5;
    int d2  = t & 31;
    int smax = (row & (TT - 1)) >> 8;
    if (smax == 0) return;               /* attn wrote these rows directly */

    float mm[NS], ll[NS];
    #pragma unroll
    for (int s = 0; s < NS; s++) {
        bool a = (s <= smax);
        mm[s] = a ? g_pm[s * ROWS + row] : -CUDART_INF_F;
        ll[s] = a ? g_pl[s * ROWS + row] : 0.f;
    }
    float2 po[NS];
    #pragma unroll
    for (int s = 0; s < NS; s++) {
        po[s] = (s <= smax)
              ? ((const float2*)g_po)[((size_t)s * ROWS + row) * 32 + d2]
              : make_float2(0.f, 0.f);
    }

    float m = -CUDART_INF_F;
    #pragma unroll
    for (int s = 0; s < NS; s++) m = fmaxf(m, mm[s]);

    float l = 0.f;
    float2 acc = make_float2(0.f, 0.f);
    #pragma unroll
    for (int s = 0; s < NS; s++) {
        float wgt = __expf(mm[s] - m);
        l += ll[s] * wgt;
        acc.x = fmaf(wgt, po[s].x, acc.x);
        acc.y = fmaf(wgt, po[s].y, acc.y);
    }
    float inv = 1.f / l;
    ((float2*)out)[(size_t)row * 32 + d2] = make_float2(acc.x * inv, acc.y * inv);
}

/* ---------------- launch ------------------------------------------------ */
extern "C" void kernel_launch(void* const* d_in, const int* in_sizes, int n_in,
                              void* d_out, int out_size) {
    (void)in_sizes; (void)n_in; (void)out_size;
    const float* x  = (const float*)d_in[0];
    const float* Wq = (const float*)d_in[1];
    const float* bq = (const float*)d_in[2];
    const float* Wk = (const float*)d_in[3];
    const float* bk = (const float*)d_in[4];
    const float* Wv = (const float*)d_in[5];

    cudaFuncSetAttribute(qkv_mma_kernel,
                         cudaFuncAttributeMaxDynamicSharedMemorySize, 2 * QBUF);

    build_b_kernel<<<dim3(16, 3), 256>>>(Wq, Wk, Wv);
    qkv_mma_kernel<<<ROWS / 64, 256, 2 * QBUF>>>(x, bq, bk);
    attn_mma_kernel<<<dim3(TRI2, BB), 256>>>((float*)d_out);
    attn_combine_kernel<<<(ROWS * 32 + 255) / 256, 256>>>((float*)d_out);
}

// round 17
// speedup vs baseline: 1.2620x; 1.2620x over previous
#include <cuda_runtime.h>
#include <cuda_bf16.h>
#include <math_constants.h>
#include <cstdint>

#define DM   1024
#define HS   64
#define BB   4
#define TT   2048
#define ROWS (BB * TT)        /* 8192 */
#define NS   8                /* key splits (SPLIT = 256) */
#define SPLIT 256
#define TRI2 72               /* sum ceil((qt+1)/2), qt=0..15 */
#define NCOL 192
#define SCV  11.541560327111707f   /* 8 * log2(e) */

typedef unsigned long long u64;

/* ---------------- helpers ------------------------------------------------ */
__device__ __forceinline__ unsigned pk_bf2(float a, float b) {
    unsigned r;
    asm("cvt.rn.bf16x2.f32 %0, %1, %2;" : "=r"(r) : "f"(b), "f"(a));
    return r;
}
__device__ __forceinline__ void mma_bf16(float* d, const unsigned* a, const unsigned* b) {
    asm volatile(
        "mma.sync.aligned.m16n8k16.row.col.f32.bf16.bf16.f32 "
        "{%0,%1,%2,%3}, {%4,%5,%6,%7}, {%8,%9}, {%0,%1,%2,%3};"
        : "+f"(d[0]), "+f"(d[1]), "+f"(d[2]), "+f"(d[3])
        : "r"(a[0]), "r"(a[1]), "r"(a[2]), "r"(a[3]), "r"(b[0]), "r"(b[1]));
}
__device__ __forceinline__ void ldsm_x4(unsigned* r, uint32_t addr) {
    asm volatile("ldmatrix.sync.aligned.m8n8.x4.shared.b16 {%0,%1,%2,%3}, [%4];"
        : "=r"(r[0]), "=r"(r[1]), "=r"(r[2]), "=r"(r[3]) : "r"(addr));
}
__device__ __forceinline__ uint32_t smem_u32(const void* p) {
    uint32_t a;
    asm("{ .reg .u64 t; cvta.to.shared.u64 t, %1; cvt.u32.u64 %0, t; }"
        : "=r"(a) : "l"(p));
    return a;
}
__device__ __forceinline__ void split4(float4 v, u64& hi, u64& lo) {
    unsigned h01 = pk_bf2(v.x, v.y), h23 = pk_bf2(v.z, v.w);
    float h0 = __uint_as_float(h01 << 16);
    float h1 = __uint_as_float(h01 & 0xffff0000u);
    float h2 = __uint_as_float(h23 << 16);
    float h3 = __uint_as_float(h23 & 0xffff0000u);
    unsigned l01 = pk_bf2(v.x - h0, v.y - h1), l23 = pk_bf2(v.z - h2, v.w - h3);
    hi = ((u64)h23 << 32) | h01;
    lo = ((u64)l23 << 32) | l01;
}

/* ---------------- device scratch ---------------------------------------- */
__device__ u64 g_Bh[NCOL * DM / 4];
__device__ u64 g_Bl[NCOL * DM / 4];
__device__ uint16_t g_qh[ROWS * HS], g_ql[ROWS * HS];
__device__ uint16_t g_kh[ROWS * HS], g_kl[ROWS * HS];
__device__ uint16_t g_vth[BB * HS * TT], g_vtl[BB * HS * TT];
__device__ float g_po[(size_t)NS * ROWS * HS];
__device__ float g_pm[NS * ROWS];
__device__ float g_pl[NS * ROWS];

/* ---------------- build fused transposed weight B[n][k] (coalesced) ----- */
__global__ __launch_bounds__(256)
void build_b_kernel(const float* __restrict__ Wq, const float* __restrict__ Wk,
                    const float* __restrict__ Wv) {
    __shared__ float s[64][65];
    const int k0    = blockIdx.x * 64;
    const int which = blockIdx.y;
    const float* __restrict__ W = (which == 0) ? Wq : ((which == 1) ? Wk : Wv);

    #pragma unroll
    for (int t = 0; t < 16; t++) {
        int idx = threadIdx.x + t * 256;
        int r = idx >> 6, c = idx & 63;
        s[r][c] = W[(size_t)(k0 + r) * HS + c];
    }
    __syncthreads();

    uint16_t* dh = (uint16_t*)g_Bh;
    uint16_t* dl = (uint16_t*)g_Bl;
    #pragma unroll
    for (int t = 0; t < 16; t++) {
        int idx = threadIdx.x + t * 256;
        int n = idx >> 6, k = idx & 63;
        float v = s[k][n];
        unsigned hp = pk_bf2(v, 0.f);
        float h = __uint_as_float(hp << 16);
        unsigned lp = pk_bf2(v - h, 0.f);
        size_t o = (size_t)(which * 64 + n) * DM + k0 + k;
        dh[o] = (uint16_t)(hp & 0xffffu);
        dl[o] = (uint16_t)(lp & 0xffffu);
    }
}

/* ---------------- fused QKV GEMM: M=64, N=192 per block (one wave) ------
 * Round-11 proven form: single smem buffer, LDG reg-prefetch, 2 syncs/chunk. */
#define QPITCH 80
#define TPITCH 132
__global__ __launch_bounds__(256)
void qkv_mma_kernel(const float* __restrict__ x,
                    const float* __restrict__ bq, const float* __restrict__ bk) {
    __shared__ __align__(128) uint8_t sbuf[40960];
    uint8_t* sAh = sbuf;
    uint8_t* sAl = sbuf + 5120;
    uint8_t* sBh = sbuf + 10240;
    uint8_t* sBl = sbuf + 25600;
    float*   sT  = (float*)sbuf;

    const int tid  = threadIdx.x;
    const int row0 = blockIdx.x * 64;
    const int w    = tid >> 5;
    const int lane = tid & 31;
    const int wm   = w & 1;
    const int wn   = w >> 1;
    const int g    = lane >> 2;
    const int tig  = lane & 3;
    const int l7   = lane & 7;
    const int q01  = (lane >> 3) & 1;
    const int q2   = lane >> 4;
    const uint32_t aBh = smem_u32(sAh), aBl = smem_u32(sAl);
    const uint32_t bBh = smem_u32(sBh), bBl = smem_u32(sBl);

    const int arow = tid >> 2, aseg = tid & 3;
    int brow_[3], bseg_[3];
    #pragma unroll
    for (int t = 0; t < 3; t++) { int i = tid + t * 256; brow_[t] = i >> 2; bseg_[t] = i & 3; }

    float acc[2][6][4];
    #pragma unroll
    for (int mt = 0; mt < 2; mt++)
        #pragma unroll
        for (int nt = 0; nt < 6; nt++)
            #pragma unroll
            for (int e = 0; e < 4; e++) acc[mt][nt][e] = 0.f;

    float4 fa0, fa1;
    ulonglong2 rb[2][3];
    {
        const float* ap = x + (size_t)(row0 + arow) * DM + aseg * 8;
        fa0 = *(const float4*)ap;
        fa1 = *(const float4*)(ap + 4);
        #pragma unroll
        for (int t = 0; t < 3; t++) {
            rb[0][t] = *(const ulonglong2*)(g_Bh + (size_t)brow_[t] * 256 + bseg_[t] * 2);
            rb[1][t] = *(const ulonglong2*)(g_Bl + (size_t)brow_[t] * 256 + bseg_[t] * 2);
        }
    }

    for (int c = 0; c < 32; c++) {
        {
            u64 h0, l0, h1, l1;
            split4(fa0, h0, l0);
            split4(fa1, h1, l1);
            ulonglong2 vh; vh.x = h0; vh.y = h1;
            ulonglong2 vl; vl.x = l0; vl.y = l1;
            *(ulonglong2*)(sAh + arow * QPITCH + aseg * 16) = vh;
            *(ulonglong2*)(sAl + arow * QPITCH + aseg * 16) = vl;
            #pragma unroll
            for (int t = 0; t < 3; t++) {
                *(ulonglong2*)(sBh + brow_[t] * QPITCH + bseg_[t] * 16) = rb[0][t];
                *(ulonglong2*)(sBl + brow_[t] * QPITCH + bseg_[t] * 16) = rb[1][t];
            }
        }
        __syncthreads();

        if (c + 1 < 32) {
            const float* ap = x + (size_t)(row0 + arow) * DM + (c + 1) * 32 + aseg * 8;
            fa0 = *(const float4*)ap;
            fa1 = *(const float4*)(ap + 4);
            #pragma unroll
            for (int t = 0; t < 3; t++) {
                rb[0][t] = *(const ulonglong2*)(g_Bh + (size_t)brow_[t] * 256
                                                + (c + 1) * 8 + bseg_[t] * 2);
                rb[1][t] = *(const ulonglong2*)(g_Bl + (size_t)brow_[t] * 256
                                                + (c + 1) * 8 + bseg_[t] * 2);
            }
        }

        #pragma unroll
        for (int ks = 0; ks < 2; ks++) {
            unsigned ah[2][4], al[2][4], bh6[3][4], bl6[3][4];
            #pragma unroll
            for (int mt = 0; mt < 2; mt++) {
                uint32_t aoff = (uint32_t)((wm * 32 + mt * 16 + q01 * 8 + l7) * QPITCH
                                           + ks * 32 + q2 * 16);
                ldsm_x4(ah[mt], aBh + aoff);
                ldsm_x4(al[mt], aBl + aoff);
            }
            #pragma unroll
            for (int p = 0; p < 3; p++) {
                uint32_t boff = (uint32_t)((wn * 48 + p * 16 + q2 * 8 + l7) * QPITCH
                                           + ks * 32 + q01 * 16);
                ldsm_x4(bh6[p], bBh + boff);
                ldsm_x4(bl6[p], bBl + boff);
            }
            #pragma unroll
            for (int mt = 0; mt < 2; mt++)
                #pragma unroll
                for (int nt = 0; nt < 6; nt++) {
                    const unsigned* bh = &bh6[nt >> 1][(nt & 1) * 2];
                    const unsigned* bl = &bl6[nt >> 1][(nt & 1) * 2];
                    mma_bf16(acc[mt][nt], ah[mt], bh);
                    mma_bf16(acc[mt][nt], ah[mt], bl);
                    mma_bf16(acc[mt][nt], al[mt], bh);
                }
        }
        __syncthreads();
    }

    #pragma unroll
    for (int mt = 0; mt < 2; mt++) {
        #pragma unroll
        for (int nt = 0; nt < 6; nt++) {
            int n_g = wn * 48 + nt * 8;
            int ml  = wm * 32 + mt * 16 + g;
            if (n_g < 128) {
                int which = n_g >> 6;
                int n = (n_g & 63) + tig * 2;
                uint16_t* dh = which ? g_kh : g_qh;
                uint16_t* dl = which ? g_kl : g_ql;
                const float* bias = which ? bk : bq;
                int m = row0 + ml;
                float bx = bias[n], by = bias[n + 1];
                float v0x = acc[mt][nt][0] + bx, v0y = acc[mt][nt][1] + by;
                float v1x = acc[mt][nt][2] + bx, v1y = acc[mt][nt][3] + by;
                unsigned h0 = pk_bf2(v0x, v0y);
                unsigned h1 = pk_bf2(v1x, v1y);
                float h0x = __uint_as_float(h0 << 16);
                float h0y = __uint_as_float(h0 & 0xffff0000u);
                float h1x = __uint_as_float(h1 << 16);
                float h1y = __uint_as_float(h1 & 0xffff0000u);
                *(unsigned*)&dh[(size_t)m * HS + n]       = h0;
                *(unsigned*)&dl[(size_t)m * HS + n]       = pk_bf2(v0x - h0x, v0y - h0y);
                *(unsigned*)&dh[(size_t)(m + 8) * HS + n] = h1;
                *(unsigned*)&dl[(size_t)(m + 8) * HS + n] = pk_bf2(v1x - h1x, v1y - h1y);
            } else {
                int nl = (n_g - 128) + tig * 2;
                sT[nl * TPITCH + ml]           = acc[mt][nt][0];
                sT[(nl + 1) * TPITCH + ml]     = acc[mt][nt][1];
                sT[nl * TPITCH + ml + 8]       = acc[mt][nt][2];
                sT[(nl + 1) * TPITCH + ml + 8] = acc[mt][nt][3];
            }
        }
    }
    __syncthreads();
    {
        const int b  = row0 >> 11;
        const int t0 = row0 & (TT - 1);
        #pragma unroll
        for (int t4 = 0; t4 < 4; t4++) {
            int idx = tid + t4 * 256;
            int d = idx >> 4, j = idx & 15;
            float4 v = *(const float4*)&sT[d * TPITCH + 4 * j];
            u64 hi, lo;
            split4(v, hi, lo);
            size_t o = ((size_t)(b * HS + d)) * TT + t0 + 4 * j;
            *(u64*)&g_vth[o] = hi;
            *(u64*)&g_vtl[o] = lo;
        }
    }
}

/* ---------------- causal flash-attention via mma.sync + ldmatrix --------
 * Round-11 body; single-split tiles (qt 0,1) finalize output directly. */
__global__ __launch_bounds__(256)
void attn_mma_kernel(float* __restrict__ out) {
    int t = blockIdx.x;            /* 0..71 */
    int b = blockIdx.y;
    int qt = 0, cum = 0;
    #pragma unroll
    for (int i = 0; i < 16; i++) {
        int cnt = (i + 2) >> 1;
        if (t < cum + cnt) { qt = i; break; }
        cum += cnt;
    }
    const int kb  = t - cum;
    const int nkb = (qt + 2) >> 1;

    const int tid  = threadIdx.x;
    const int w    = tid >> 5;
    const int lane = tid & 31;
    const int g    = lane >> 2;
    const int tig  = lane & 3;
    const int r0   = qt * 128 + w * 16;
    const int bT   = b * TT;
    const int kend = qt * 128 + 128;

    __shared__ __align__(128) uint8_t sKh[64 * 144];
    __shared__ __align__(128) uint8_t sKl[64 * 144];
    __shared__ __align__(128) uint8_t sVh[64 * 144];
    __shared__ __align__(128) uint8_t sVl[64 * 144];

    const uint32_t kBh = smem_u32(sKh), kBl = smem_u32(sKl);
    const uint32_t vBh = smem_u32(sVh), vBl = smem_u32(sVl);
    const int l7 = lane & 7;
    const int q4 = lane >> 3;

    unsigned qh[4][4], ql[4][4];
    {
        const uint16_t* qah = g_qh + (size_t)(bT + r0 + g) * HS;
        const uint16_t* qal = g_ql + (size_t)(bT + r0 + g) * HS;
        #pragma unroll
        for (int kq = 0; kq < 4; kq++) {
            int c = kq * 16 + 2 * tig;
            qh[kq][0] = *(const unsigned*)(qah + c);
            qh[kq][1] = *(const unsigned*)(qah + 8 * HS + c);
            qh[kq][2] = *(const unsigned*)(qah + c + 8);
            qh[kq][3] = *(const unsigned*)(qah + 8 * HS + c + 8);
            ql[kq][0] = *(const unsigned*)(qal + c);
            ql[kq][1] = *(const unsigned*)(qal + 8 * HS + c);
            ql[kq][2] = *(const unsigned*)(qal + c + 8);
            ql[kq][3] = *(const unsigned*)(qal + 8 * HS + c + 8);
        }
    }

    float o[8][4];
    #pragma unroll
    for (int i = 0; i < 8; i++)
        #pragma unroll
        for (int e = 0; e < 4; e++) o[i][e] = 0.f;
    float m_a = -CUDART_INF_F, m_b = -CUDART_INF_F;
    float l_a = 0.f, l_b = 0.f;
    const int ra = r0 + g, rb = r0 + g + 8;

    for (int c2 = 0; c2 < 4; c2++) {
        const int j0 = kb * SPLIT + c2 * 64;
        if (j0 >= kend) break;
        __syncthreads();
        #pragma unroll
        for (int t4 = 0; t4 < 4; t4++) {
            int i = tid + t4 * 256;
            int row = i >> 4, c8 = i & 15;
            *(u64*)(sKh + row * 144 + c8 * 8) =
                *(const u64*)(g_kh + (size_t)(bT + j0 + row) * HS + c8 * 4);
            *(u64*)(sKl + row * 144 + c8 * 8) =
                *(const u64*)(g_kl + (size_t)(bT + j0 + row) * HS + c8 * 4);
            *(u64*)(sVh + row * 144 + c8 * 8) =
                *(const u64*)(g_vth + (size_t)(b * HS + row) * TT + j0 + c8 * 4);
            *(u64*)(sVl + row * 144 + c8 * 8) =
                *(const u64*)(g_vtl + (size_t)(b * HS + row) * TT + j0 + c8 * 4);
        }
        __syncthreads();

        if (j0 > r0 + 15) continue;

        float sc[8][4];
        #pragma unroll
        for (int nt = 0; nt < 8; nt++)
            #pragma unroll
            for (int e = 0; e < 4; e++) sc[nt][e] = 0.f;

        #pragma unroll
        for (int nt = 0; nt < 8; nt++) {
            unsigned kh[8], kl[8];
            uint32_t rowoff = (uint32_t)((nt * 8 + l7) * 144 + q4 * 16);
            ldsm_x4(kh,     kBh + rowoff);
            ldsm_x4(kh + 4, kBh + rowoff + 64);
            ldsm_x4(kl,     kBl + rowoff);
            ldsm_x4(kl + 4, kBl + rowoff + 64);
            #pragma unroll
            for (int kk = 0; kk < 4; kk++) {
                mma_bf16(sc[nt], qh[kk], kh + kk * 2);
                mma_bf16(sc[nt], qh[kk], kl + kk * 2);
                mma_bf16(sc[nt], ql[kk], kh + kk * 2);
            }
        }

        float mxa = -CUDART_INF_F, mxb = -CUDART_INF_F;
        #pragma unroll
        for (int nt = 0; nt < 8; nt++) {
            int jc = j0 + nt * 8 + 2 * tig;
            if (jc     > ra) sc[nt][0] = -CUDART_INF_F;
            if (jc + 1 > ra) sc[nt][1] = -CUDART_INF_F;
            if (jc     > rb) sc[nt][2] = -CUDART_INF_F;
            if (jc + 1 > rb) sc[nt][3] = -CUDART_INF_F;
            mxa = fmaxf(mxa, fmaxf(sc[nt][0], sc[nt][1]));
            mxb = fmaxf(mxb, fmaxf(sc[nt][2], sc[nt][3]));
        }
        mxa = fmaxf(mxa, __shfl_xor_sync(0xffffffffu, mxa, 1));
        mxa = fmaxf(mxa, __shfl_xor_sync(0xffffffffu, mxa, 2));
        mxb = fmaxf(mxb, __shfl_xor_sync(0xffffffffu, mxb, 1));
        mxb = fmaxf(mxb, __shfl_xor_sync(0xffffffffu, mxb, 2));

        float mna = fmaxf(m_a, mxa), mnb = fmaxf(m_b, mxb);
        float alpha_a = exp2f((m_a - mna) * SCV);
        float alpha_b = exp2f((m_b - mnb) * SCV);
        m_a = mna; m_b = mnb;

        float p[8][4];
        float laa = 0.f, lba = 0.f;
        #pragma unroll
        for (int nt = 0; nt < 8; nt++) {
            p[nt][0] = exp2f((sc[nt][0] - mna) * SCV);
            p[nt][1] = exp2f((sc[nt][1] - mna) * SCV);
            p[nt][2] = exp2f((sc[nt][2] - mnb) * SCV);
            p[nt][3] = exp2f((sc[nt][3] - mnb) * SCV);
            laa += p[nt][0] + p[nt][1];
            lba += p[nt][2] + p[nt][3];
        }
        laa += __shfl_xor_sync(0xffffffffu, laa, 1);
        laa += __shfl_xor_sync(0xffffffffu, laa, 2);
        lba += __shfl_xor_sync(0xffffffffu, lba, 1);
        lba += __shfl_xor_sync(0xffffffffu, lba, 2);
        l_a = l_a * alpha_a + laa;
        l_b = l_b * alpha_b + lba;

        #pragma unroll
        for (int nt = 0; nt < 8; nt++) {
            o[nt][0] *= alpha_a; o[nt][1] *= alpha_a;
            o[nt][2] *= alpha_b; o[nt][3] *= alpha_b;
        }

        unsigned ph[4][4], pl[4][4];
        #pragma unroll
        for (int k2 = 0; k2 < 4; k2++) {
            int n0 = 2 * k2, n1 = 2 * k2 + 1;
            #pragma unroll
            for (int e = 0; e < 4; e++) {
                int nt = (e < 2) ? n0 : n1;
                int e0 = (e & 1) ? 2 : 0;
                float pa = p[nt][e0], pb = p[nt][e0 + 1];
                unsigned hp = pk_bf2(pa, pb);
                float ha = __uint_as_float(hp << 16);
                float hb = __uint_as_float(hp & 0xffff0000u);
                ph[k2][e] = hp;
                pl[k2][e] = pk_bf2(pa - ha, pb - hb);
            }
        }

        #pragma unroll
        for (int nt = 0; nt < 8; nt++) {
            unsigned vh[8], vl[8];
            uint32_t rowoff = (uint32_t)((nt * 8 + l7) * 144 + q4 * 16);
            ldsm_x4(vh,     vBh + rowoff);
            ldsm_x4(vh + 4, vBh + rowoff + 64);
            ldsm_x4(vl,     vBl + rowoff);
            ldsm_x4(vl + 4, vBl + rowoff + 64);
            #pragma unroll
            for (int k2 = 0; k2 < 4; k2++) {
                mma_bf16(o[nt], ph[k2], vh + k2 * 2);
                mma_bf16(o[nt], ph[k2], vl + k2 * 2);
                mma_bf16(o[nt], pl[k2], vh + k2 * 2);
            }
        }
    }

    if (nkb == 1) {
        /* single split: finalize directly, no partials (validated round 16) */
        float inv_a = 1.f / l_a, inv_b = 1.f / l_b;
        #pragma unroll
        for (int nt = 0; nt < 8; nt++) {
            *(float2*)&out[((size_t)(bT + ra)) * HS + nt * 8 + 2 * tig] =
                make_float2(o[nt][0] * inv_a, o[nt][1] * inv_a);
            *(float2*)&out[((size_t)(bT + rb)) * HS + nt * 8 + 2 * tig] =
                make_float2(o[nt][2] * inv_b, o[nt][3] * inv_b);
        }
        return;
    }

    size_t pa_off = ((size_t)kb * ROWS + bT + ra) * HS;
    size_t pb_off = ((size_t)kb * ROWS + bT + rb) * HS;
    #pragma unroll
    for (int nt = 0; nt < 8; nt++) {
        *(float2*)&g_po[pa_off + nt * 8 + 2 * tig] = make_float2(o[nt][0], o[nt][1]);
        *(float2*)&g_po[pb_off + nt * 8 + 2 * tig] = make_float2(o[nt][2], o[nt][3]);
    }
    if (tig == 0) {
        g_pm[kb * ROWS + bT + ra] = m_a * 8.0f;
        g_pl[kb * ROWS + bT + ra] = l_a;
        g_pm[kb * ROWS + bT + rb] = m_b * 8.0f;
        g_pl[kb * ROWS + bT + rb] = l_b;
    }
}

/* ---------------- combine split partials (multi-split rows only) --------- */
__global__ __launch_bounds__(256)
void attn_combine_kernel(float* __restrict__ out) {
    int t = blockIdx.x * blockDim.x + threadIdx.x;
    if (t >= ROWS * 32) return;
    int row = t >> 5;
    int d2  = t & 31;
    int smax = (row & (TT - 1)) >> 8;
    if (smax == 0) return;               /* attn wrote these rows directly */

    float mm[NS], ll[NS];
    #pragma unroll
    for (int s = 0; s < NS; s++) {
        bool a = (s <= smax);
        mm[s] = a ? g_pm[s * ROWS + row] : -CUDART_INF_F;
        ll[s] = a ? g_pl[s * ROWS + row] : 0.f;
    }
    float2 po[NS];
    #pragma unroll
    for (int s = 0; s < NS; s++) {
        po[s] = (s <= smax)
              ? ((const float2*)g_po)[((size_t)s * ROWS + row) * 32 + d2]
              : make_float2(0.f, 0.f);
    }

    float m = -CUDART_INF_F;
    #pragma unroll
    for (int s = 0; s < NS; s++) m = fmaxf(m, mm[s]);

    float l = 0.f;
    float2 acc = make_float2(0.f, 0.f);
    #pragma unroll
    for (int s = 0; s < NS; s++) {
        float wgt = __expf(mm[s] - m);
        l += ll[s] * wgt;
        acc.x = fmaf(wgt, po[s].x, acc.x);
        acc.y = fmaf(wgt, po[s].y, acc.y);
    }
    float inv = 1.f / l;
    ((float2*)out)[(size_t)row * 32 + d2] = make_float2(acc.x * inv, acc.y * inv);
}

/* ---------------- launch ------------------------------------------------ */
extern "C" void kernel_launch(void* const* d_in, const int* in_sizes, int n_in,
                              void* d_out, int out_size) {
    (void)in_sizes; (void)n_in; (void)out_size;
    const float* x  = (const float*)d_in[0];
    const float* Wq = (const float*)d_in[1];
    const float* bq = (const float*)d_in[2];
    const float* Wk = (const float*)d_in[3];
    const float* bk = (const float*)d_in[4];
    const float* Wv = (const float*)d_in[5];

    build_b_kernel<<<dim3(16, 3), 256>>>(Wq, Wk, Wv);
    qkv_mma_kernel<<<ROWS / 64, 256>>>(x, bq, bk);
    attn_mma_kernel<<<dim3(TRI2, BB), 256>>>((float*)d_out);
    attn_combine_kernel<<<(ROWS * 32 + 255) / 256, 256>>>((float*)d_out);
}